// round 15
// baseline (speedup 1.0000x reference)
#include <cuda_runtime.h>
#include <cuda_bf16.h>
#include <stdint.h>
#include <math.h>

#define DIM   128
#define MAXN  50000
#define MAXE  1600000
#define ND    (MAXN * DIM)
#define NDH   (MAXN * 64)

#define ASTR  68
#define A_HI  0
#define A_LO  8704
#define B_HI  17408
#define B_LO  26112
#define SMEM_BYTES 139264

#define SCAN_BLK 1024
#define MAX_PARTS 64

// ---------------- device scratch ----------------
__device__ int      g_deg[MAXN + 1];
__device__ int      g_rowptr[MAXN + 1];
__device__ int      g_cursor[MAXN + 1];
__device__ int      g_part[MAX_PARTS];
__device__ int      g_csrc[MAXE];
__device__ float    g_u[2 * ND];
__device__ float    g_h[2 * ND];
__device__ float    g_eps[ND];
__device__ uint32_t g_xbf[NDH];          // packed bf16x2 x
__device__ uint32_t g_hbf[4 * NDH];      // [path][slot] packed bf16x2 h
__device__ uint32_t g_wprep[14 * 16384];

// ---------------- bf16 helpers ----------------
__device__ __forceinline__ uint32_t pack2bf(float x, float y) {
    unsigned short sx = __bfloat16_as_ushort(__float2bfloat16(x));
    unsigned short sy = __bfloat16_as_ushort(__float2bfloat16(y));
    return (uint32_t)sx | ((uint32_t)sy << 16);
}
__device__ __forceinline__ float bf_res(float x) {
    return x - __bfloat162float(__float2bfloat16(x));
}
__device__ __forceinline__ float bf_lo_f(uint32_t w) { return __uint_as_float(w << 16); }
__device__ __forceinline__ float bf_hi_f(uint32_t w) { return __uint_as_float(w & 0xFFFF0000u); }

__device__ __forceinline__ void mma_bf16(float* c, uint32_t a0, uint32_t a1, uint32_t a2,
                                         uint32_t a3, uint32_t b0, uint32_t b1) {
    asm volatile(
        "mma.sync.aligned.m16n8k16.row.col.f32.bf16.bf16.f32 "
        "{%0,%1,%2,%3},{%4,%5,%6,%7},{%8,%9},{%0,%1,%2,%3};"
        : "+f"(c[0]), "+f"(c[1]), "+f"(c[2]), "+f"(c[3])
        : "r"(a0), "r"(a1), "r"(a2), "r"(a3), "r"(b0), "r"(b1));
}

// ---------------- weight prep ----------------
struct PrepArgs { const float* src[14]; };

__global__ void prep_kernel(PrepArgs a) {
    extern __shared__ float tile[];          // 128 x 130
    const float* W = a.src[blockIdx.x];
    uint32_t* dhi = g_wprep + blockIdx.x * 16384;
    uint32_t* dlo = dhi + 8192;
    for (int idx = threadIdx.x; idx < 16384; idx += blockDim.x) {
        int k = idx >> 7, nc = idx & 127;
        tile[nc * 130 + k] = __ldg(&W[idx]);
    }
    __syncthreads();
    for (int idx = threadIdx.x; idx < 8192; idx += blockDim.x) {
        int nrow = idx >> 6, kp = idx & 63;
        float v0 = tile[nrow * 130 + kp * 2];
        float v1 = tile[nrow * 130 + kp * 2 + 1];
        dhi[idx] = pack2bf(v0, v1);
        dlo[idx] = pack2bf(bf_res(v0), bf_res(v1));
    }
}

// ---------------- x -> packed bf16 (persistent small grid) ----------------
__global__ void xconv_kernel(const float* __restrict__ x, uint32_t* __restrict__ xbf,
                             int words) {
    int stride = gridDim.x * blockDim.x;
    const float2* x2 = (const float2*)x;
    for (int i = blockIdx.x * blockDim.x + threadIdx.x; i < words; i += stride) {
        float2 v = __ldg(&x2[i]);
        xbf[i] = pack2bf(v.x, v.y);
    }
}

// ---------------- CSR build ----------------
__global__ void zero_deg_kernel(int n) {
    int i = blockIdx.x * blockDim.x + threadIdx.x;
    if (i <= n) g_deg[i] = 0;
}
__global__ void hist_kernel(const int* __restrict__ dst, int e) {
    int i = blockIdx.x * blockDim.x + threadIdx.x;
    if (i < e) atomicAdd(&g_deg[dst[i]], 1);
}
__global__ void scan_p1(int n) {
    __shared__ int sd[32];
    int i = blockIdx.x * SCAN_BLK + threadIdx.x;
    int v = (i < n) ? g_deg[i] : 0;
#pragma unroll
    for (int o = 16; o > 0; o >>= 1) v += __shfl_xor_sync(0xffffffffu, v, o);
    if ((threadIdx.x & 31) == 0) sd[threadIdx.x >> 5] = v;
    __syncthreads();
    if (threadIdx.x < 32) {
        int s = sd[threadIdx.x];
#pragma unroll
        for (int o = 16; o > 0; o >>= 1) s += __shfl_xor_sync(0xffffffffu, s, o);
        if (threadIdx.x == 0) g_part[blockIdx.x] = s;
    }
}
__global__ void scan_p2(int nb) {
    int t = threadIdx.x;
    int v0 = (2 * t < nb) ? g_part[2 * t] : 0;
    int v1 = (2 * t + 1 < nb) ? g_part[2 * t + 1] : 0;
    int s = v0 + v1;
    int incl = s;
#pragma unroll
    for (int o = 1; o < 32; o <<= 1) {
        int u = __shfl_up_sync(0xffffffffu, incl, o);
        if (t >= o) incl += u;
    }
    int excl = incl - s;
    if (2 * t < MAX_PARTS) g_part[2 * t] = excl;
    if (2 * t + 1 < MAX_PARTS) g_part[2 * t + 1] = excl + v0;
}
__global__ void scan_p3(int n) {
    __shared__ int sw[32];
    int b = blockIdx.x, t = threadIdx.x;
    int i = b * SCAN_BLK + t;
    int v = (i < n) ? g_deg[i] : 0;
    int lane = t & 31, w = t >> 5;
    int incl = v;
#pragma unroll
    for (int o = 1; o < 32; o <<= 1) {
        int u = __shfl_up_sync(0xffffffffu, incl, o);
        if (lane >= o) incl += u;
    }
    if (lane == 31) sw[w] = incl;
    __syncthreads();
    if (t < 32) {
        int s = sw[t];
        int si = s;
#pragma unroll
        for (int o = 1; o < 32; o <<= 1) {
            int u = __shfl_up_sync(0xffffffffu, si, o);
            if (t >= o) si += u;
        }
        sw[t] = si - s;
    }
    __syncthreads();
    int excl = incl - v + sw[w] + g_part[b];
    if (i < n) {
        g_rowptr[i] = excl;
        g_cursor[i] = excl;
        if (i == n - 1) g_rowptr[n] = excl + v;
    }
}
__global__ void fill_kernel(const int* __restrict__ src, const int* __restrict__ dst, int e) {
    int i = blockIdx.x * blockDim.x + threadIdx.x;
    if (i < e) {
        int p = atomicAdd(&g_cursor[dst[i]], 1);
        g_csrc[p] = src[i];
    }
}

// ---------------- layer-0 SpMM over packed bf16 x (paths share gather) ----------------
__global__ void spmm0_bf_kernel(const uint32_t* __restrict__ xbf,
                                const float* __restrict__ epsm, const float* __restrict__ epss,
                                float* __restrict__ um, float* __restrict__ us, int n) {
    int gw = (blockIdx.x * blockDim.x + threadIdx.x) >> 5;
    int lane = threadIdx.x & 31;
    if (gw >= n) return;
    int rp0 = g_rowptr[gw], rp1 = g_rowptr[gw + 1];
    const uint2* x2 = (const uint2*)xbf;
    float a0 = 0.f, a1 = 0.f, a2 = 0.f, a3 = 0.f;
#pragma unroll 2
    for (int j = rp0; j < rp1; ++j) {
        int s = __ldg(&g_csrc[j]);
        uint2 w = __ldg(&x2[(size_t)s * 32 + lane]);
        a0 += bf_lo_f(w.x); a1 += bf_hi_f(w.x);
        a2 += bf_lo_f(w.y); a3 += bf_hi_f(w.y);
    }
    float cm = 1.0f + __ldg(&epsm[0]);
    float cs = 1.0f + __ldg(&epss[0]);
    uint2 hw = __ldg(&x2[(size_t)gw * 32 + lane]);
    float h0 = bf_lo_f(hw.x), h1 = bf_hi_f(hw.x);
    float h2 = bf_lo_f(hw.y), h3 = bf_hi_f(hw.y);
    float4 om, os;
    om.x = fmaf(cm, h0, a0); om.y = fmaf(cm, h1, a1);
    om.z = fmaf(cm, h2, a2); om.w = fmaf(cm, h3, a3);
    os.x = fmaf(cs, h0, a0); os.y = fmaf(cs, h1, a1);
    os.z = fmaf(cs, h2, a2); os.w = fmaf(cs, h3, a3);
    ((float4*)um)[(size_t)gw * 32 + lane] = om;
    ((float4*)us)[(size_t)gw * 32 + lane] = os;
}

// ---------------- per-path SpMM over packed bf16 h (half traffic) ----------------
__global__ void spmm1_bf_kernel(const uint32_t* __restrict__ hbf,
                                const float* __restrict__ epsv, int layer,
                                float* __restrict__ u, int n) {
    int gw = (blockIdx.x * blockDim.x + threadIdx.x) >> 5;
    int lane = threadIdx.x & 31;
    if (gw >= n) return;
    int rp0 = g_rowptr[gw], rp1 = g_rowptr[gw + 1];
    const uint2* h2 = (const uint2*)hbf;
    float a0 = 0.f, a1 = 0.f, a2 = 0.f, a3 = 0.f;
#pragma unroll 2
    for (int j = rp0; j < rp1; ++j) {
        int s = __ldg(&g_csrc[j]);
        uint2 w = __ldg(&h2[(size_t)s * 32 + lane]);
        a0 += bf_lo_f(w.x); a1 += bf_hi_f(w.x);
        a2 += bf_lo_f(w.y); a3 += bf_hi_f(w.y);
    }
    float c = 1.0f + __ldg(&epsv[layer]);
    uint2 hw = __ldg(&h2[(size_t)gw * 32 + lane]);
    float4 o;
    o.x = fmaf(c, bf_lo_f(hw.x), a0);
    o.y = fmaf(c, bf_hi_f(hw.x), a1);
    o.z = fmaf(c, bf_lo_f(hw.y), a2);
    o.w = fmaf(c, bf_hi_f(hw.y), a3);
    ((float4*)u)[(size_t)gw * 32 + lane] = o;
}

// ---------------- shared GEMM pieces ----------------
__device__ __forceinline__ void load_A_bf(const float* __restrict__ U, int row0, int n,
                                          uint32_t* smw, int t) {
    int row = t >> 1, half = t & 1;
    int r = row0 + row;
    const float4* u4 = (const float4*)U + (size_t)r * 32 + half * 16;
    uint32_t* ah = smw + A_HI + row * ASTR + half * 32;
    uint32_t* al = smw + A_LO + row * ASTR + half * 32;
#pragma unroll 4
    for (int q = 0; q < 16; q++) {
        float4 v = make_float4(0.f, 0.f, 0.f, 0.f);
        if (r < n) v = __ldg(&u4[q]);
        ah[q * 2]     = pack2bf(v.x, v.y);
        al[q * 2]     = pack2bf(bf_res(v.x), bf_res(v.y));
        ah[q * 2 + 1] = pack2bf(v.z, v.w);
        al[q * 2 + 1] = pack2bf(bf_res(v.z), bf_res(v.w));
    }
}

__device__ __forceinline__ void copy_W(const uint32_t* __restrict__ Wp, uint32_t* smw, int t) {
    const uint4* s4 = (const uint4*)Wp;
#pragma unroll
    for (int i = 0; i < 8; i++) {
        int j = t + i * 256;
        int nrow = j >> 4, kp = (j & 15) * 4;
        *(uint4*)(smw + B_HI + nrow * ASTR + kp) = __ldg(&s4[j]);
        *(uint4*)(smw + B_LO + nrow * ASTR + kp) = __ldg(&s4[j + 2048]);
    }
}

__device__ __forceinline__ void gemm_pass(const uint32_t* __restrict__ smw, int aoff, int boff,
                                          float acc[2][8][4], int ra, int kq, int nb) {
#pragma unroll
    for (int kk = 0; kk < 8; kk++) {
        int kp0 = kk * 8 + kq, kp1 = kp0 + 4;
        uint32_t a[2][4];
#pragma unroll
        for (int i = 0; i < 2; i++) {
            int rb = aoff + (ra + i * 16) * ASTR;
            a[i][0] = smw[rb + kp0];
            a[i][1] = smw[rb + 8 * ASTR + kp0];
            a[i][2] = smw[rb + kp1];
            a[i][3] = smw[rb + 8 * ASTR + kp1];
        }
#pragma unroll
        for (int j = 0; j < 8; j++) {
            int bb = boff + (nb + j * 8) * ASTR;
            uint32_t b0 = smw[bb + kp0], b1 = smw[bb + kp1];
            mma_bf16(acc[0][j], a[0][0], a[0][1], a[0][2], a[0][3], b0, b1);
            mma_bf16(acc[1][j], a[1][0], a[1][1], a[1][2], a[1][3], b0, b1);
        }
    }
}

__device__ __forceinline__ void gemm3(const uint32_t* smw, float acc[2][8][4],
                                      int ra, int kq, int nb) {
    gemm_pass(smw, A_HI, B_HI, acc, ra, kq, nb);
    gemm_pass(smw, A_HI, B_LO, acc, ra, kq, nb);
    gemm_pass(smw, A_LO, B_HI, acc, ra, kq, nb);
}

__device__ __forceinline__ void zero_acc(float acc[2][8][4]) {
#pragma unroll
    for (int i = 0; i < 2; i++)
#pragma unroll
        for (int j = 0; j < 8; j++)
#pragma unroll
            for (int q = 0; q < 4; q++) acc[i][j][q] = 0.f;
}

__device__ __forceinline__ float sigf(float x) { return 1.0f / (1.0f + expf(-x)); }

// ---------------- MLP layer (single path) ----------------
struct MlpP { const float* U; const uint32_t* W1p; const uint32_t* W2p;
              const float* b1; const float* b2; float* Hf; uint32_t* Hbf; };

__global__ __launch_bounds__(256, 1) void mlp_mma_kernel(MlpP P, int n) {
    extern __shared__ uint32_t smw[];
    int row0 = blockIdx.x * 128;
    int t = threadIdx.x, lane = t & 31, wid = t >> 5;
    int wm = wid >> 1, wn = wid & 1;
    int ra = wm * 32 + (lane >> 2);
    int kq = lane & 3;
    int nb = wn * 64 + (lane >> 2);

    load_A_bf(P.U, row0, n, smw, t);
    copy_W(P.W1p, smw, t);
    __syncthreads();

    float acc[2][8][4];
    zero_acc(acc);
    gemm3(smw, acc, ra, kq, nb);
    __syncthreads();

#pragma unroll
    for (int i = 0; i < 2; i++) {
#pragma unroll
        for (int j = 0; j < 8; j++) {
            int rl = wm * 32 + i * 16 + (lane >> 2);
            int c0 = wn * 64 + j * 8 + 2 * kq;
            float s0 = sigf(acc[i][j][0] + __ldg(&P.b1[c0]));
            float s1 = sigf(acc[i][j][1] + __ldg(&P.b1[c0 + 1]));
            float s2 = sigf(acc[i][j][2] + __ldg(&P.b1[c0]));
            float s3 = sigf(acc[i][j][3] + __ldg(&P.b1[c0 + 1]));
            int kp = wn * 32 + j * 4 + kq;
            smw[A_HI + rl * ASTR + kp] = pack2bf(s0, s1);
            smw[A_LO + rl * ASTR + kp] = pack2bf(bf_res(s0), bf_res(s1));
            smw[A_HI + (rl + 8) * ASTR + kp] = pack2bf(s2, s3);
            smw[A_LO + (rl + 8) * ASTR + kp] = pack2bf(bf_res(s2), bf_res(s3));
        }
    }
    copy_W(P.W2p, smw, t);
    __syncthreads();

    zero_acc(acc);
    gemm3(smw, acc, ra, kq, nb);

#pragma unroll
    for (int i = 0; i < 2; i++) {
#pragma unroll
        for (int j = 0; j < 8; j++) {
            int gr = row0 + wm * 32 + i * 16 + (lane >> 2);
            int c0 = wn * 64 + j * 8 + 2 * kq;
            float bb0 = __ldg(&P.b2[c0]), bb1 = __ldg(&P.b2[c0 + 1]);
            float v0 = acc[i][j][0] + bb0, v1 = acc[i][j][1] + bb1;
            float v2 = acc[i][j][2] + bb0, v3 = acc[i][j][3] + bb1;
            if (P.Hf) {
                if (gr < n)
                    *(float2*)(P.Hf + (size_t)gr * DIM + c0) = make_float2(v0, v1);
                if (gr + 8 < n)
                    *(float2*)(P.Hf + (size_t)(gr + 8) * DIM + c0) = make_float2(v2, v3);
            } else {
                int wc = (c0 >> 1);
                if (gr < n) P.Hbf[(size_t)gr * 64 + wc] = pack2bf(v0, v1);
                if (gr + 8 < n) P.Hbf[(size_t)(gr + 8) * 64 + wc] = pack2bf(v2, v3);
            }
        }
    }
}

// ---------------- final (single path): LN(Hin @ Wout + bout) -> out section ----------------
struct FinP { const float* Hin; const uint32_t* Wp; const float* bo; };

__global__ __launch_bounds__(256, 1) void final_mma_kernel(FinP P,
                                                           const float* __restrict__ gamma,
                                                           const float* __restrict__ beta,
                                                           float* __restrict__ out,
                                                           int sect, int n) {
    extern __shared__ uint32_t smw[];
    int row0 = blockIdx.x * 128;
    int t = threadIdx.x, lane = t & 31, wid = t >> 5;
    int wm = wid >> 1, wn = wid & 1;
    int ra = wm * 32 + (lane >> 2);
    int kq = lane & 3;
    int nb = wn * 64 + (lane >> 2);

    load_A_bf(P.Hin, row0, n, smw, t);
    copy_W(P.Wp, smw, t);
    __syncthreads();

    float acc[2][8][4];
    zero_acc(acc);
    gemm3(smw, acc, ra, kq, nb);
    __syncthreads();

    float* gS = (float*)smw;
#pragma unroll
    for (int i = 0; i < 2; i++) {
#pragma unroll
        for (int j = 0; j < 8; j++) {
            int rl = wm * 32 + i * 16 + (lane >> 2);
            int c0 = wn * 64 + j * 8 + 2 * kq;
            float bb0 = __ldg(&P.bo[c0]), bb1 = __ldg(&P.bo[c0 + 1]);
            gS[rl * 133 + c0]       = acc[i][j][0] + bb0;
            gS[rl * 133 + c0 + 1]   = acc[i][j][1] + bb1;
            gS[(rl + 8) * 133 + c0]     = acc[i][j][2] + bb0;
            gS[(rl + 8) * 133 + c0 + 1] = acc[i][j][3] + bb1;
        }
    }
    __syncthreads();

    if (t < 128) {
        int r = row0 + t;
        if (r < n) {
            const float* rowp = gS + t * 133;
            float sum = 0.f;
#pragma unroll 8
            for (int c = 0; c < 128; c++) sum += rowp[c];
            float mean = sum * (1.0f / 128.0f);
            float ss = 0.f;
#pragma unroll 8
            for (int c = 0; c < 128; c++) {
                float d = rowp[c] - mean;
                ss += d * d;
            }
            float inv = rsqrtf(ss * (1.0f / 128.0f) + 1e-5f);
            float* op = out + (size_t)sect * (size_t)n * DIM + (size_t)r * DIM;
#pragma unroll 4
            for (int c = 0; c < 128; c += 4) {
                float4 o;
                o.x = fmaf((rowp[c]     - mean) * inv, __ldg(&gamma[c]),     __ldg(&beta[c]));
                o.y = fmaf((rowp[c + 1] - mean) * inv, __ldg(&gamma[c + 1]), __ldg(&beta[c + 1]));
                o.z = fmaf((rowp[c + 2] - mean) * inv, __ldg(&gamma[c + 2]), __ldg(&beta[c + 2]));
                o.w = fmaf((rowp[c + 3] - mean) * inv, __ldg(&gamma[c + 3]), __ldg(&beta[c + 3]));
                *(float4*)(op + c) = o;
            }
        }
    }
}

// ---------------- threefry noise (persistent grid) + light sample join ----------------
__device__ __forceinline__ uint32_t rotl32(uint32_t x, int r) {
    return (x << r) | (x >> (32 - r));
}
__device__ __forceinline__ float bits_to_normal(uint32_t b) {
    uint32_t fb = (b >> 9) | 0x3F800000u;
    float u = __uint_as_float(fb) - 1.0f;
    const float lo = -0.99999994f;
    float v = fmaf(u, 2.0f, lo);
    v = fmaxf(v, lo);
    float w = -log1pf(-v * v);
    float p;
    if (w < 5.0f) {
        w -= 2.5f;
        p = 2.81022636e-08f;
        p = fmaf(p, w, 3.43273939e-07f);
        p = fmaf(p, w, -3.5233877e-06f);
        p = fmaf(p, w, -4.39150654e-06f);
        p = fmaf(p, w, 0.00021858087f);
        p = fmaf(p, w, -0.00125372503f);
        p = fmaf(p, w, -0.00417768164f);
        p = fmaf(p, w, 0.246640727f);
        p = fmaf(p, w, 1.50140941f);
    } else {
        w = sqrtf(w) - 3.0f;
        p = -0.000200214257f;
        p = fmaf(p, w, 0.000100950558f);
        p = fmaf(p, w, 0.00134934322f);
        p = fmaf(p, w, -0.00367342844f);
        p = fmaf(p, w, 0.00573950773f);
        p = fmaf(p, w, -0.0076224613f);
        p = fmaf(p, w, 0.00943887047f);
        p = fmaf(p, w, 1.00167406f);
        p = fmaf(p, w, 2.83297682f);
    }
    return 1.41421356237f * (p * v);
}

__global__ void noise_kernel(float* __restrict__ eps, int total) {
    int stride = gridDim.x * blockDim.x;
    for (int f = blockIdx.x * blockDim.x + threadIdx.x; f < total; f += stride) {
        const uint32_t ks0 = 0u, ks1 = 42u;
        const uint32_t ks2 = ks0 ^ ks1 ^ 0x1BD11BDAu;
        uint32_t x0 = 0u + ks0;
        uint32_t x1 = (uint32_t)f + ks1;
#define TFR(r) { x0 += x1; x1 = rotl32(x1, (r)) ^ x0; }
        TFR(13) TFR(15) TFR(26) TFR(6)   x0 += ks1; x1 += ks2 + 1u;
        TFR(17) TFR(29) TFR(16) TFR(24)  x0 += ks2; x1 += ks0 + 2u;
        TFR(13) TFR(15) TFR(26) TFR(6)   x0 += ks0; x1 += ks1 + 3u;
        TFR(17) TFR(29) TFR(16) TFR(24)  x0 += ks1; x1 += ks2 + 4u;
        TFR(13) TFR(15) TFR(26) TFR(6)   x0 += ks2; x1 += ks0 + 5u;
#undef TFR
        eps[f] = bits_to_normal(x0 ^ x1);
    }
}

__global__ void sample_kernel(float* __restrict__ out, const float* __restrict__ eps,
                              int total4) {
    int f = blockIdx.x * blockDim.x + threadIdx.x;
    if (f >= total4) return;
    const float4* mv = (const float4*)out + total4;
    const float4* sv = (const float4*)out + 2 * (size_t)total4;
    float4 ev = __ldg(&((const float4*)eps)[f]);
    float4 m = __ldg(&mv[f]);
    float4 s = __ldg(&sv[f]);
    float4 o;
    o.x = fmaf(ev.x, s.x, m.x);
    o.y = fmaf(ev.y, s.y, m.y);
    o.z = fmaf(ev.z, s.z, m.z);
    o.w = fmaf(ev.w, s.w, m.w);
    ((float4*)out)[f] = o;
}

// ---------------- persistent stream/event handles ----------------
static cudaStream_t s_sM = nullptr, s_sS = nullptr, s_sN = nullptr;
static cudaEvent_t  s_ev0, s_evP, s_evF, s_evX, s_evR, s_evM, s_evS, s_evN;

// ---------------- launch ----------------
extern "C" void kernel_launch(void* const* d_in, const int* in_sizes, int n_in,
                              void* d_out, int out_size) {
    const float* x    = (const float*)d_in[0];
    const int*   esrc = (const int*)d_in[1];
    const int*   edst = (const int*)d_in[2];
    const float* mW1  = (const float*)d_in[3];
    const float* mb1  = (const float*)d_in[4];
    const float* mW2  = (const float*)d_in[5];
    const float* mb2  = (const float*)d_in[6];
    const float* meps = (const float*)d_in[7];
    const float* mWo  = (const float*)d_in[8];
    const float* mbo  = (const float*)d_in[9];
    const float* sW1  = (const float*)d_in[10];
    const float* sb1  = (const float*)d_in[11];
    const float* sW2  = (const float*)d_in[12];
    const float* sb2  = (const float*)d_in[13];
    const float* seps = (const float*)d_in[14];
    const float* sWo  = (const float*)d_in[15];
    const float* sbo  = (const float*)d_in[16];
    const float* lng  = (const float*)d_in[17];
    const float* lnb  = (const float*)d_in[18];

    int n = in_sizes[0] / DIM;
    int e = in_sizes[1];
    int total = n * DIM;
    float* out = (float*)d_out;

    void* p;
    cudaGetSymbolAddress(&p, g_u); float* u0 = (float*)p; float* u1 = u0 + ND;
    cudaGetSymbolAddress(&p, g_h); float* h0 = (float*)p; float* h1 = h0 + ND;
    cudaGetSymbolAddress(&p, g_eps); float* epsbuf = (float*)p;
    cudaGetSymbolAddress(&p, g_xbf); uint32_t* xbf = (uint32_t*)p;
    cudaGetSymbolAddress(&p, g_hbf); uint32_t* hb = (uint32_t*)p;
    uint32_t* hb00 = hb;            uint32_t* hb01 = hb + NDH;
    uint32_t* hb10 = hb + 2 * NDH;  uint32_t* hb11 = hb + 3 * NDH;
    cudaGetSymbolAddress(&p, g_wprep); uint32_t* wp = (uint32_t*)p;

    cudaFuncSetAttribute(mlp_mma_kernel, cudaFuncAttributeMaxDynamicSharedMemorySize, SMEM_BYTES);
    cudaFuncSetAttribute(final_mma_kernel, cudaFuncAttributeMaxDynamicSharedMemorySize, SMEM_BYTES);
    cudaFuncSetAttribute(prep_kernel, cudaFuncAttributeMaxDynamicSharedMemorySize, 128 * 130 * 4);

    if (s_sM == nullptr) {
        cudaStreamCreateWithFlags(&s_sM, cudaStreamNonBlocking);
        cudaStreamCreateWithFlags(&s_sS, cudaStreamNonBlocking);
        cudaStreamCreateWithFlags(&s_sN, cudaStreamNonBlocking);
        cudaEventCreateWithFlags(&s_ev0, cudaEventDisableTiming);
        cudaEventCreateWithFlags(&s_evP, cudaEventDisableTiming);
        cudaEventCreateWithFlags(&s_evF, cudaEventDisableTiming);
        cudaEventCreateWithFlags(&s_evX, cudaEventDisableTiming);
        cudaEventCreateWithFlags(&s_evR, cudaEventDisableTiming);
        cudaEventCreateWithFlags(&s_evM, cudaEventDisableTiming);
        cudaEventCreateWithFlags(&s_evS, cudaEventDisableTiming);
        cudaEventCreateWithFlags(&s_evN, cudaEventDisableTiming);
    }
    cudaStream_t sM = s_sM, sS = s_sS, sN = s_sN;

    // fork point
    cudaEventRecord(s_ev0, 0);
    cudaStreamWaitEvent(sM, s_ev0, 0);
    cudaStreamWaitEvent(sN, s_ev0, 0);

    // x -> bf16 on sN (persistent 148-CTA grid, hidden under the CSR build)
    xconv_kernel<<<148, 256, 0, sN>>>(x, xbf, total / 2);
    cudaEventRecord(s_evX, sN);

    // weight prep on sM, overlapping CSR build on the default stream
    PrepArgs pa;
    for (int pth = 0; pth < 2; pth++) {
        const float* W1 = pth ? sW1 : mW1;
        const float* W2 = pth ? sW2 : mW2;
        const float* Wo = pth ? sWo : mWo;
        for (int l = 0; l < 3; l++) {
            pa.src[pth * 7 + l * 2 + 0] = W1 + l * 16384;
            pa.src[pth * 7 + l * 2 + 1] = W2 + l * 16384;
        }
        pa.src[pth * 7 + 6] = Wo;
    }
    prep_kernel<<<14, 256, 128 * 130 * 4, sM>>>(pa);
    cudaEventRecord(s_evP, sM);

    // CSR by destination (default stream)
    int nblk = (n + SCAN_BLK - 1) / SCAN_BLK;
    zero_deg_kernel<<<(n + 256) / 256, 256>>>(n);
    hist_kernel<<<(e + 255) / 256, 256>>>(edst, e);
    scan_p1<<<nblk, SCAN_BLK>>>(n);
    scan_p2<<<1, 32>>>(nblk);
    scan_p3<<<nblk, SCAN_BLK>>>(n);
    fill_kernel<<<(e + 255) / 256, 256>>>(esrc, edst, e);
    cudaEventRecord(s_evF, 0);

    int spmm_blocks = (n * 32 + 255) / 256;
    int gx = (n + 127) / 128;

    // noise: persistent 148-CTA grid on sN, co-runs with spmm0
    cudaStreamWaitEvent(sN, s_evF, 0);
    noise_kernel<<<148, 256, 0, sN>>>(epsbuf, total);
    cudaEventRecord(s_evN, sN);

    // layer 0: shared bf16 x gather (default stream), then symmetric fork
    cudaStreamWaitEvent(0, s_evX, 0);
    spmm0_bf_kernel<<<spmm_blocks, 256>>>(xbf, meps, seps, u0, u1, n);
    cudaEventRecord(s_evR, 0);
    cudaStreamWaitEvent(sM, s_evR, 0);
    cudaStreamWaitEvent(sS, s_evR, 0);
    cudaStreamWaitEvent(sS, s_evP, 0);

#define WSLOT(pth, idx) (wp + ((pth) * 7 + (idx)) * 16384)

    // path M (mean) on sM
    mlp_mma_kernel<<<gx, 256, SMEM_BYTES, sM>>>(
        MlpP{u0, WSLOT(0, 0), WSLOT(0, 1), mb1, mb2, nullptr, hb00}, n);
    spmm1_bf_kernel<<<spmm_blocks, 256, 0, sM>>>(hb00, meps, 1, u0, n);
    mlp_mma_kernel<<<gx, 256, SMEM_BYTES, sM>>>(
        MlpP{u0, WSLOT(0, 2), WSLOT(0, 3), mb1 + DIM, mb2 + DIM, nullptr, hb01}, n);
    spmm1_bf_kernel<<<spmm_blocks, 256, 0, sM>>>(hb01, meps, 2, u0, n);
    mlp_mma_kernel<<<gx, 256, SMEM_BYTES, sM>>>(
        MlpP{u0, WSLOT(0, 4), WSLOT(0, 5), mb1 + 2 * DIM, mb2 + 2 * DIM, h0, nullptr}, n);
    final_mma_kernel<<<gx, 256, SMEM_BYTES, sM>>>(
        FinP{h0, WSLOT(0, 6), mbo}, lng, lnb, out, 1, n);
    cudaEventRecord(s_evM, sM);

    // path S (std) on sS
    mlp_mma_kernel<<<gx, 256, SMEM_BYTES, sS>>>(
        MlpP{u1, WSLOT(1, 0), WSLOT(1, 1), sb1, sb2, nullptr, hb10}, n);
    spmm1_bf_kernel<<<spmm_blocks, 256, 0, sS>>>(hb10, seps, 1, u1, n);
    mlp_mma_kernel<<<gx, 256, SMEM_BYTES, sS>>>(
        MlpP{u1, WSLOT(1, 2), WSLOT(1, 3), sb1 + DIM, sb2 + DIM, nullptr, hb11}, n);
    spmm1_bf_kernel<<<spmm_blocks, 256, 0, sS>>>(hb11, seps, 2, u1, n);
    mlp_mma_kernel<<<gx, 256, SMEM_BYTES, sS>>>(
        MlpP{u1, WSLOT(1, 4), WSLOT(1, 5), sb1 + 2 * DIM, sb2 + 2 * DIM, h1, nullptr}, n);
    final_mma_kernel<<<gx, 256, SMEM_BYTES, sS>>>(
        FinP{h1, WSLOT(1, 6), sbo}, lng, lnb, out, 2, n);
    cudaEventRecord(s_evS, sS);

    // join and light sample on default stream
    cudaStreamWaitEvent(0, s_evM, 0);
    cudaStreamWaitEvent(0, s_evS, 0);
    cudaStreamWaitEvent(0, s_evN, 0);
    sample_kernel<<<(total / 4 + 255) / 256, 256>>>(out, epsbuf, total / 4);
}

// round 16
// speedup vs baseline: 1.0413x; 1.0413x over previous
#include <cuda_runtime.h>
#include <cuda_bf16.h>
#include <stdint.h>
#include <math.h>

#define DIM   128
#define MAXN  50000
#define MAXE  1600000
#define ND    (MAXN * DIM)
#define NDH   (MAXN * 64)

#define ASTR  68
#define A_HI  0
#define A_LO  8704
#define B_HI  17408
#define B_LO  26112
#define SMEM_BYTES 139264

#define SCAN_BLK 1024
#define MAX_PARTS 64

// ---------------- device scratch ----------------
__device__ int      g_deg[MAXN + 1];
__device__ int      g_rowptr[MAXN + 1];
__device__ int      g_cursor[MAXN + 1];
__device__ int      g_part[MAX_PARTS];
__device__ int      g_csrc[MAXE];
__device__ float    g_u[2 * ND];
__device__ float    g_h[2 * ND];
__device__ float    g_eps[ND];
__device__ uint32_t g_hbf[4 * NDH];      // [path][slot] packed bf16x2 h
__device__ uint32_t g_wprep[14 * 16384];

// ---------------- bf16 helpers ----------------
__device__ __forceinline__ uint32_t pack2bf(float x, float y) {
    unsigned short sx = __bfloat16_as_ushort(__float2bfloat16(x));
    unsigned short sy = __bfloat16_as_ushort(__float2bfloat16(y));
    return (uint32_t)sx | ((uint32_t)sy << 16);
}
__device__ __forceinline__ float bf_res(float x) {
    return x - __bfloat162float(__float2bfloat16(x));
}
__device__ __forceinline__ float bf_lo_f(uint32_t w) { return __uint_as_float(w << 16); }
__device__ __forceinline__ float bf_hi_f(uint32_t w) { return __uint_as_float(w & 0xFFFF0000u); }

__device__ __forceinline__ void mma_bf16(float* c, uint32_t a0, uint32_t a1, uint32_t a2,
                                         uint32_t a3, uint32_t b0, uint32_t b1) {
    asm volatile(
        "mma.sync.aligned.m16n8k16.row.col.f32.bf16.bf16.f32 "
        "{%0,%1,%2,%3},{%4,%5,%6,%7},{%8,%9},{%0,%1,%2,%3};"
        : "+f"(c[0]), "+f"(c[1]), "+f"(c[2]), "+f"(c[3])
        : "r"(a0), "r"(a1), "r"(a2), "r"(a3), "r"(b0), "r"(b1));
}

// ---------------- weight prep ----------------
struct PrepArgs { const float* src[14]; };

__global__ void prep_kernel(PrepArgs a) {
    extern __shared__ float tile[];          // 128 x 130
    const float* W = a.src[blockIdx.x];
    uint32_t* dhi = g_wprep + blockIdx.x * 16384;
    uint32_t* dlo = dhi + 8192;
    for (int idx = threadIdx.x; idx < 16384; idx += blockDim.x) {
        int k = idx >> 7, nc = idx & 127;
        tile[nc * 130 + k] = __ldg(&W[idx]);
    }
    __syncthreads();
    for (int idx = threadIdx.x; idx < 8192; idx += blockDim.x) {
        int nrow = idx >> 6, kp = idx & 63;
        float v0 = tile[nrow * 130 + kp * 2];
        float v1 = tile[nrow * 130 + kp * 2 + 1];
        dhi[idx] = pack2bf(v0, v1);
        dlo[idx] = pack2bf(bf_res(v0), bf_res(v1));
    }
}

// ---------------- CSR build ----------------
__global__ void zero_deg_kernel(int n) {
    int i = blockIdx.x * blockDim.x + threadIdx.x;
    if (i <= n) g_deg[i] = 0;
}
__global__ void hist_kernel(const int* __restrict__ dst, int e) {
    int i = blockIdx.x * blockDim.x + threadIdx.x;
    if (i < e) atomicAdd(&g_deg[dst[i]], 1);
}
__global__ void scan_p1(int n) {
    __shared__ int sd[32];
    int i = blockIdx.x * SCAN_BLK + threadIdx.x;
    int v = (i < n) ? g_deg[i] : 0;
#pragma unroll
    for (int o = 16; o > 0; o >>= 1) v += __shfl_xor_sync(0xffffffffu, v, o);
    if ((threadIdx.x & 31) == 0) sd[threadIdx.x >> 5] = v;
    __syncthreads();
    if (threadIdx.x < 32) {
        int s = sd[threadIdx.x];
#pragma unroll
        for (int o = 16; o > 0; o >>= 1) s += __shfl_xor_sync(0xffffffffu, s, o);
        if (threadIdx.x == 0) g_part[blockIdx.x] = s;
    }
}
__global__ void scan_p2(int nb) {
    int t = threadIdx.x;
    int v0 = (2 * t < nb) ? g_part[2 * t] : 0;
    int v1 = (2 * t + 1 < nb) ? g_part[2 * t + 1] : 0;
    int s = v0 + v1;
    int incl = s;
#pragma unroll
    for (int o = 1; o < 32; o <<= 1) {
        int u = __shfl_up_sync(0xffffffffu, incl, o);
        if (t >= o) incl += u;
    }
    int excl = incl - s;
    if (2 * t < MAX_PARTS) g_part[2 * t] = excl;
    if (2 * t + 1 < MAX_PARTS) g_part[2 * t + 1] = excl + v0;
}
__global__ void scan_p3(int n) {
    __shared__ int sw[32];
    int b = blockIdx.x, t = threadIdx.x;
    int i = b * SCAN_BLK + t;
    int v = (i < n) ? g_deg[i] : 0;
    int lane = t & 31, w = t >> 5;
    int incl = v;
#pragma unroll
    for (int o = 1; o < 32; o <<= 1) {
        int u = __shfl_up_sync(0xffffffffu, incl, o);
        if (lane >= o) incl += u;
    }
    if (lane == 31) sw[w] = incl;
    __syncthreads();
    if (t < 32) {
        int s = sw[t];
        int si = s;
#pragma unroll
        for (int o = 1; o < 32; o <<= 1) {
            int u = __shfl_up_sync(0xffffffffu, si, o);
            if (t >= o) si += u;
        }
        sw[t] = si - s;
    }
    __syncthreads();
    int excl = incl - v + sw[w] + g_part[b];
    if (i < n) {
        g_rowptr[i] = excl;
        g_cursor[i] = excl;
        if (i == n - 1) g_rowptr[n] = excl + v;
    }
}
__global__ void fill_kernel(const int* __restrict__ src, const int* __restrict__ dst, int e) {
    int i = blockIdx.x * blockDim.x + threadIdx.x;
    if (i < e) {
        int p = atomicAdd(&g_cursor[dst[i]], 1);
        g_csrc[p] = src[i];
    }
}

// ---------------- layer-0 SpMM (fp32 x, paths share gather) ----------------
__global__ void spmm0_kernel(const float* __restrict__ x,
                             const float* __restrict__ epsm, const float* __restrict__ epss,
                             float* __restrict__ um, float* __restrict__ us, int n) {
    int gw = (blockIdx.x * blockDim.x + threadIdx.x) >> 5;
    int lane = threadIdx.x & 31;
    if (gw >= n) return;
    int rp0 = g_rowptr[gw], rp1 = g_rowptr[gw + 1];
    const float4* x4 = (const float4*)x;
    float4 am = make_float4(0.f, 0.f, 0.f, 0.f);
#pragma unroll 2
    for (int j = rp0; j < rp1; ++j) {
        int s = __ldg(&g_csrc[j]);
        float4 v = __ldg(&x4[(size_t)s * 32 + lane]);
        am.x += v.x; am.y += v.y; am.z += v.z; am.w += v.w;
    }
    float cm = 1.0f + __ldg(&epsm[0]);
    float cs = 1.0f + __ldg(&epss[0]);
    float4 h0 = __ldg(&x4[(size_t)gw * 32 + lane]);
    float4 om, os;
    om.x = fmaf(cm, h0.x, am.x); om.y = fmaf(cm, h0.y, am.y);
    om.z = fmaf(cm, h0.z, am.z); om.w = fmaf(cm, h0.w, am.w);
    os.x = fmaf(cs, h0.x, am.x); os.y = fmaf(cs, h0.y, am.y);
    os.z = fmaf(cs, h0.z, am.z); os.w = fmaf(cs, h0.w, am.w);
    ((float4*)um)[(size_t)gw * 32 + lane] = om;
    ((float4*)us)[(size_t)gw * 32 + lane] = os;
}

// ---------------- per-path SpMM over packed bf16 h (half traffic) ----------------
__global__ void spmm1_bf_kernel(const uint32_t* __restrict__ hbf,
                                const float* __restrict__ epsv, int layer,
                                float* __restrict__ u, int n) {
    int gw = (blockIdx.x * blockDim.x + threadIdx.x) >> 5;
    int lane = threadIdx.x & 31;
    if (gw >= n) return;
    int rp0 = g_rowptr[gw], rp1 = g_rowptr[gw + 1];
    const uint2* h2 = (const uint2*)hbf;    // row = 32 uint2 (64 words = 128 bf16)
    float a0 = 0.f, a1 = 0.f, a2 = 0.f, a3 = 0.f;
#pragma unroll 2
    for (int j = rp0; j < rp1; ++j) {
        int s = __ldg(&g_csrc[j]);
        uint2 w = __ldg(&h2[(size_t)s * 32 + lane]);
        a0 += bf_lo_f(w.x); a1 += bf_hi_f(w.x);
        a2 += bf_lo_f(w.y); a3 += bf_hi_f(w.y);
    }
    float c = 1.0f + __ldg(&epsv[layer]);
    uint2 hw = __ldg(&h2[(size_t)gw * 32 + lane]);
    float4 o;
    o.x = fmaf(c, bf_lo_f(hw.x), a0);
    o.y = fmaf(c, bf_hi_f(hw.x), a1);
    o.z = fmaf(c, bf_lo_f(hw.y), a2);
    o.w = fmaf(c, bf_hi_f(hw.y), a3);
    ((float4*)u)[(size_t)gw * 32 + lane] = o;
}

// ---------------- shared GEMM pieces ----------------
__device__ __forceinline__ void load_A_bf(const float* __restrict__ U, int row0, int n,
                                          uint32_t* smw, int t) {
    int row = t >> 1, half = t & 1;
    int r = row0 + row;
    const float4* u4 = (const float4*)U + (size_t)r * 32 + half * 16;
    uint32_t* ah = smw + A_HI + row * ASTR + half * 32;
    uint32_t* al = smw + A_LO + row * ASTR + half * 32;
#pragma unroll 4
    for (int q = 0; q < 16; q++) {
        float4 v = make_float4(0.f, 0.f, 0.f, 0.f);
        if (r < n) v = __ldg(&u4[q]);
        ah[q * 2]     = pack2bf(v.x, v.y);
        al[q * 2]     = pack2bf(bf_res(v.x), bf_res(v.y));
        ah[q * 2 + 1] = pack2bf(v.z, v.w);
        al[q * 2 + 1] = pack2bf(bf_res(v.z), bf_res(v.w));
    }
}

__device__ __forceinline__ void copy_W(const uint32_t* __restrict__ Wp, uint32_t* smw, int t) {
    const uint4* s4 = (const uint4*)Wp;
#pragma unroll
    for (int i = 0; i < 8; i++) {
        int j = t + i * 256;
        int nrow = j >> 4, kp = (j & 15) * 4;
        *(uint4*)(smw + B_HI + nrow * ASTR + kp) = __ldg(&s4[j]);
        *(uint4*)(smw + B_LO + nrow * ASTR + kp) = __ldg(&s4[j + 2048]);
    }
}

__device__ __forceinline__ void gemm_pass(const uint32_t* __restrict__ smw, int aoff, int boff,
                                          float acc[2][8][4], int ra, int kq, int nb) {
#pragma unroll
    for (int kk = 0; kk < 8; kk++) {
        int kp0 = kk * 8 + kq, kp1 = kp0 + 4;
        uint32_t a[2][4];
#pragma unroll
        for (int i = 0; i < 2; i++) {
            int rb = aoff + (ra + i * 16) * ASTR;
            a[i][0] = smw[rb + kp0];
            a[i][1] = smw[rb + 8 * ASTR + kp0];
            a[i][2] = smw[rb + kp1];
            a[i][3] = smw[rb + 8 * ASTR + kp1];
        }
#pragma unroll
        for (int j = 0; j < 8; j++) {
            int bb = boff + (nb + j * 8) * ASTR;
            uint32_t b0 = smw[bb + kp0], b1 = smw[bb + kp1];
            mma_bf16(acc[0][j], a[0][0], a[0][1], a[0][2], a[0][3], b0, b1);
            mma_bf16(acc[1][j], a[1][0], a[1][1], a[1][2], a[1][3], b0, b1);
        }
    }
}

__device__ __forceinline__ void gemm3(const uint32_t* smw, float acc[2][8][4],
                                      int ra, int kq, int nb) {
    gemm_pass(smw, A_HI, B_HI, acc, ra, kq, nb);
    gemm_pass(smw, A_HI, B_LO, acc, ra, kq, nb);
    gemm_pass(smw, A_LO, B_HI, acc, ra, kq, nb);
}

__device__ __forceinline__ void zero_acc(float acc[2][8][4]) {
#pragma unroll
    for (int i = 0; i < 2; i++)
#pragma unroll
        for (int j = 0; j < 8; j++)
#pragma unroll
            for (int q = 0; q < 4; q++) acc[i][j][q] = 0.f;
}

__device__ __forceinline__ float sigf(float x) { return 1.0f / (1.0f + expf(-x)); }

// ---------------- MLP layer (single path) ----------------
// Hf != nullptr: write fp32 H; else write packed bf16 to Hbf (256B/row)
struct MlpP { const float* U; const uint32_t* W1p; const uint32_t* W2p;
              const float* b1; const float* b2; float* Hf; uint32_t* Hbf; };

__global__ __launch_bounds__(256, 1) void mlp_mma_kernel(MlpP P, int n) {
    extern __shared__ uint32_t smw[];
    int row0 = blockIdx.x * 128;
    int t = threadIdx.x, lane = t & 31, wid = t >> 5;
    int wm = wid >> 1, wn = wid & 1;
    int ra = wm * 32 + (lane >> 2);
    int kq = lane & 3;
    int nb = wn * 64 + (lane >> 2);

    load_A_bf(P.U, row0, n, smw, t);
    copy_W(P.W1p, smw, t);
    __syncthreads();

    float acc[2][8][4];
    zero_acc(acc);
    gemm3(smw, acc, ra, kq, nb);
    __syncthreads();

#pragma unroll
    for (int i = 0; i < 2; i++) {
#pragma unroll
        for (int j = 0; j < 8; j++) {
            int rl = wm * 32 + i * 16 + (lane >> 2);
            int c0 = wn * 64 + j * 8 + 2 * kq;
            float s0 = sigf(acc[i][j][0] + __ldg(&P.b1[c0]));
            float s1 = sigf(acc[i][j][1] + __ldg(&P.b1[c0 + 1]));
            float s2 = sigf(acc[i][j][2] + __ldg(&P.b1[c0]));
            float s3 = sigf(acc[i][j][3] + __ldg(&P.b1[c0 + 1]));
            int kp = wn * 32 + j * 4 + kq;
            smw[A_HI + rl * ASTR + kp] = pack2bf(s0, s1);
            smw[A_LO + rl * ASTR + kp] = pack2bf(bf_res(s0), bf_res(s1));
            smw[A_HI + (rl + 8) * ASTR + kp] = pack2bf(s2, s3);
            smw[A_LO + (rl + 8) * ASTR + kp] = pack2bf(bf_res(s2), bf_res(s3));
        }
    }
    copy_W(P.W2p, smw, t);
    __syncthreads();

    zero_acc(acc);
    gemm3(smw, acc, ra, kq, nb);

#pragma unroll
    for (int i = 0; i < 2; i++) {
#pragma unroll
        for (int j = 0; j < 8; j++) {
            int gr = row0 + wm * 32 + i * 16 + (lane >> 2);
            int c0 = wn * 64 + j * 8 + 2 * kq;
            float bb0 = __ldg(&P.b2[c0]), bb1 = __ldg(&P.b2[c0 + 1]);
            float v0 = acc[i][j][0] + bb0, v1 = acc[i][j][1] + bb1;
            float v2 = acc[i][j][2] + bb0, v3 = acc[i][j][3] + bb1;
            if (P.Hf) {
                if (gr < n)
                    *(float2*)(P.Hf + (size_t)gr * DIM + c0) = make_float2(v0, v1);
                if (gr + 8 < n)
                    *(float2*)(P.Hf + (size_t)(gr + 8) * DIM + c0) = make_float2(v2, v3);
            } else {
                int wc = (c0 >> 1);          // word column 0..63
                if (gr < n) P.Hbf[(size_t)gr * 64 + wc] = pack2bf(v0, v1);
                if (gr + 8 < n) P.Hbf[(size_t)(gr + 8) * 64 + wc] = pack2bf(v2, v3);
            }
        }
    }
}

// ---------------- final (single path): LN(Hin @ Wout + bout) -> out section ----------------
struct FinP { const float* Hin; const uint32_t* Wp; const float* bo; };

__global__ __launch_bounds__(256, 1) void final_mma_kernel(FinP P,
                                                           const float* __restrict__ gamma,
                                                           const float* __restrict__ beta,
                                                           float* __restrict__ out,
                                                           int sect, int n) {
    extern __shared__ uint32_t smw[];
    int row0 = blockIdx.x * 128;
    int t = threadIdx.x, lane = t & 31, wid = t >> 5;
    int wm = wid >> 1, wn = wid & 1;
    int ra = wm * 32 + (lane >> 2);
    int kq = lane & 3;
    int nb = wn * 64 + (lane >> 2);

    load_A_bf(P.Hin, row0, n, smw, t);
    copy_W(P.Wp, smw, t);
    __syncthreads();

    float acc[2][8][4];
    zero_acc(acc);
    gemm3(smw, acc, ra, kq, nb);
    __syncthreads();

    float* gS = (float*)smw;
#pragma unroll
    for (int i = 0; i < 2; i++) {
#pragma unroll
        for (int j = 0; j < 8; j++) {
            int rl = wm * 32 + i * 16 + (lane >> 2);
            int c0 = wn * 64 + j * 8 + 2 * kq;
            float bb0 = __ldg(&P.bo[c0]), bb1 = __ldg(&P.bo[c0 + 1]);
            gS[rl * 133 + c0]       = acc[i][j][0] + bb0;
            gS[rl * 133 + c0 + 1]   = acc[i][j][1] + bb1;
            gS[(rl + 8) * 133 + c0]     = acc[i][j][2] + bb0;
            gS[(rl + 8) * 133 + c0 + 1] = acc[i][j][3] + bb1;
        }
    }
    __syncthreads();

    if (t < 128) {
        int r = row0 + t;
        if (r < n) {
            const float* rowp = gS + t * 133;
            float sum = 0.f;
#pragma unroll 8
            for (int c = 0; c < 128; c++) sum += rowp[c];
            float mean = sum * (1.0f / 128.0f);
            float ss = 0.f;
#pragma unroll 8
            for (int c = 0; c < 128; c++) {
                float d = rowp[c] - mean;
                ss += d * d;
            }
            float inv = rsqrtf(ss * (1.0f / 128.0f) + 1e-5f);
            float* op = out + (size_t)sect * (size_t)n * DIM + (size_t)r * DIM;
#pragma unroll 4
            for (int c = 0; c < 128; c += 4) {
                float4 o;
                o.x = fmaf((rowp[c]     - mean) * inv, __ldg(&gamma[c]),     __ldg(&beta[c]));
                o.y = fmaf((rowp[c + 1] - mean) * inv, __ldg(&gamma[c + 1]), __ldg(&beta[c + 1]));
                o.z = fmaf((rowp[c + 2] - mean) * inv, __ldg(&gamma[c + 2]), __ldg(&beta[c + 2]));
                o.w = fmaf((rowp[c + 3] - mean) * inv, __ldg(&gamma[c + 3]), __ldg(&beta[c + 3]));
                *(float4*)(op + c) = o;
            }
        }
    }
}

// ---------------- threefry noise (persistent grid) + light sample join ----------------
__device__ __forceinline__ uint32_t rotl32(uint32_t x, int r) {
    return (x << r) | (x >> (32 - r));
}
__device__ __forceinline__ float bits_to_normal(uint32_t b) {
    uint32_t fb = (b >> 9) | 0x3F800000u;
    float u = __uint_as_float(fb) - 1.0f;
    const float lo = -0.99999994f;
    float v = fmaf(u, 2.0f, lo);
    v = fmaxf(v, lo);
    float w = -log1pf(-v * v);
    float p;
    if (w < 5.0f) {
        w -= 2.5f;
        p = 2.81022636e-08f;
        p = fmaf(p, w, 3.43273939e-07f);
        p = fmaf(p, w, -3.5233877e-06f);
        p = fmaf(p, w, -4.39150654e-06f);
        p = fmaf(p, w, 0.00021858087f);
        p = fmaf(p, w, -0.00125372503f);
        p = fmaf(p, w, -0.00417768164f);
        p = fmaf(p, w, 0.246640727f);
        p = fmaf(p, w, 1.50140941f);
    } else {
        w = sqrtf(w) - 3.0f;
        p = -0.000200214257f;
        p = fmaf(p, w, 0.000100950558f);
        p = fmaf(p, w, 0.00134934322f);
        p = fmaf(p, w, -0.00367342844f);
        p = fmaf(p, w, 0.00573950773f);
        p = fmaf(p, w, -0.0076224613f);
        p = fmaf(p, w, 0.00943887047f);
        p = fmaf(p, w, 1.00167406f);
        p = fmaf(p, w, 2.83297682f);
    }
    return 1.41421356237f * (p * v);
}

__global__ void noise_kernel(float* __restrict__ eps, int total) {
    int stride = gridDim.x * blockDim.x;
    for (int f = blockIdx.x * blockDim.x + threadIdx.x; f < total; f += stride) {
        const uint32_t ks0 = 0u, ks1 = 42u;
        const uint32_t ks2 = ks0 ^ ks1 ^ 0x1BD11BDAu;
        uint32_t x0 = 0u + ks0;
        uint32_t x1 = (uint32_t)f + ks1;
#define TFR(r) { x0 += x1; x1 = rotl32(x1, (r)) ^ x0; }
        TFR(13) TFR(15) TFR(26) TFR(6)   x0 += ks1; x1 += ks2 + 1u;
        TFR(17) TFR(29) TFR(16) TFR(24)  x0 += ks2; x1 += ks0 + 2u;
        TFR(13) TFR(15) TFR(26) TFR(6)   x0 += ks0; x1 += ks1 + 3u;
        TFR(17) TFR(29) TFR(16) TFR(24)  x0 += ks1; x1 += ks2 + 4u;
        TFR(13) TFR(15) TFR(26) TFR(6)   x0 += ks2; x1 += ks0 + 5u;
#undef TFR
        eps[f] = bits_to_normal(x0 ^ x1);
    }
}

__global__ void sample_kernel(float* __restrict__ out, const float* __restrict__ eps,
                              int total4) {
    int f = blockIdx.x * blockDim.x + threadIdx.x;
    if (f >= total4) return;
    const float4* mv = (const float4*)out + total4;
    const float4* sv = (const float4*)out + 2 * (size_t)total4;
    float4 ev = __ldg(&((const float4*)eps)[f]);
    float4 m = __ldg(&mv[f]);
    float4 s = __ldg(&sv[f]);
    float4 o;
    o.x = fmaf(ev.x, s.x, m.x);
    o.y = fmaf(ev.y, s.y, m.y);
    o.z = fmaf(ev.z, s.z, m.z);
    o.w = fmaf(ev.w, s.w, m.w);
    ((float4*)out)[f] = o;
}

// ---------------- persistent stream/event handles ----------------
static cudaStream_t s_sM = nullptr, s_sS = nullptr, s_sN = nullptr;
static cudaEvent_t  s_ev0, s_evP, s_evF, s_evR, s_evM, s_evS, s_evN;

// ---------------- launch ----------------
extern "C" void kernel_launch(void* const* d_in, const int* in_sizes, int n_in,
                              void* d_out, int out_size) {
    const float* x    = (const float*)d_in[0];
    const int*   esrc = (const int*)d_in[1];
    const int*   edst = (const int*)d_in[2];
    const float* mW1  = (const float*)d_in[3];
    const float* mb1  = (const float*)d_in[4];
    const float* mW2  = (const float*)d_in[5];
    const float* mb2  = (const float*)d_in[6];
    const float* meps = (const float*)d_in[7];
    const float* mWo  = (const float*)d_in[8];
    const float* mbo  = (const float*)d_in[9];
    const float* sW1  = (const float*)d_in[10];
    const float* sb1  = (const float*)d_in[11];
    const float* sW2  = (const float*)d_in[12];
    const float* sb2  = (const float*)d_in[13];
    const float* seps = (const float*)d_in[14];
    const float* sWo  = (const float*)d_in[15];
    const float* sbo  = (const float*)d_in[16];
    const float* lng  = (const float*)d_in[17];
    const float* lnb  = (const float*)d_in[18];

    int n = in_sizes[0] / DIM;
    int e = in_sizes[1];
    int total = n * DIM;
    float* out = (float*)d_out;

    void* p;
    cudaGetSymbolAddress(&p, g_u); float* u0 = (float*)p; float* u1 = u0 + ND;
    cudaGetSymbolAddress(&p, g_h); float* h0 = (float*)p; float* h1 = h0 + ND;
    cudaGetSymbolAddress(&p, g_eps); float* epsbuf = (float*)p;
    cudaGetSymbolAddress(&p, g_hbf); uint32_t* hb = (uint32_t*)p;
    uint32_t* hb00 = hb;            uint32_t* hb01 = hb + NDH;
    uint32_t* hb10 = hb + 2 * NDH;  uint32_t* hb11 = hb + 3 * NDH;
    cudaGetSymbolAddress(&p, g_wprep); uint32_t* wp = (uint32_t*)p;

    cudaFuncSetAttribute(mlp_mma_kernel, cudaFuncAttributeMaxDynamicSharedMemorySize, SMEM_BYTES);
    cudaFuncSetAttribute(final_mma_kernel, cudaFuncAttributeMaxDynamicSharedMemorySize, SMEM_BYTES);
    cudaFuncSetAttribute(prep_kernel, cudaFuncAttributeMaxDynamicSharedMemorySize, 128 * 130 * 4);

    if (s_sM == nullptr) {
        cudaStreamCreateWithFlags(&s_sM, cudaStreamNonBlocking);
        cudaStreamCreateWithFlags(&s_sS, cudaStreamNonBlocking);
        cudaStreamCreateWithFlags(&s_sN, cudaStreamNonBlocking);
        cudaEventCreateWithFlags(&s_ev0, cudaEventDisableTiming);
        cudaEventCreateWithFlags(&s_evP, cudaEventDisableTiming);
        cudaEventCreateWithFlags(&s_evF, cudaEventDisableTiming);
        cudaEventCreateWithFlags(&s_evR, cudaEventDisableTiming);
        cudaEventCreateWithFlags(&s_evM, cudaEventDisableTiming);
        cudaEventCreateWithFlags(&s_evS, cudaEventDisableTiming);
        cudaEventCreateWithFlags(&s_evN, cudaEventDisableTiming);
    }
    cudaStream_t sM = s_sM, sS = s_sS, sN = s_sN;

    // fork point
    cudaEventRecord(s_ev0, 0);
    cudaStreamWaitEvent(sM, s_ev0, 0);

    // weight prep on sM, overlapping CSR build on the default stream
    PrepArgs pa;
    for (int pth = 0; pth < 2; pth++) {
        const float* W1 = pth ? sW1 : mW1;
        const float* W2 = pth ? sW2 : mW2;
        const float* Wo = pth ? sWo : mWo;
        for (int l = 0; l < 3; l++) {
            pa.src[pth * 7 + l * 2 + 0] = W1 + l * 16384;
            pa.src[pth * 7 + l * 2 + 1] = W2 + l * 16384;
        }
        pa.src[pth * 7 + 6] = Wo;
    }
    prep_kernel<<<14, 256, 128 * 130 * 4, sM>>>(pa);
    cudaEventRecord(s_evP, sM);

    // CSR by destination (default stream)
    int nblk = (n + SCAN_BLK - 1) / SCAN_BLK;
    zero_deg_kernel<<<(n + 256) / 256, 256>>>(n);
    hist_kernel<<<(e + 255) / 256, 256>>>(edst, e);
    scan_p1<<<nblk, SCAN_BLK>>>(n);
    scan_p2<<<1, 32>>>(nblk);
    scan_p3<<<nblk, SCAN_BLK>>>(n);
    fill_kernel<<<(e + 255) / 256, 256>>>(esrc, edst, e);
    cudaEventRecord(s_evF, 0);

    int spmm_blocks = (n * 32 + 255) / 256;
    int gx = (n + 127) / 128;

    // noise: persistent 148-CTA grid on sN, co-runs with spmm0
    cudaStreamWaitEvent(sN, s_evF, 0);
    noise_kernel<<<148, 256, 0, sN>>>(epsbuf, total);
    cudaEventRecord(s_evN, sN);

    // layer 0: shared x gather (default stream), then symmetric fork
    spmm0_kernel<<<spmm_blocks, 256>>>(x, meps, seps, u0, u1, n);
    cudaEventRecord(s_evR, 0);
    cudaStreamWaitEvent(sM, s_evR, 0);
    cudaStreamWaitEvent(sS, s_evR, 0);
    cudaStreamWaitEvent(sS, s_evP, 0);

#define WSLOT(pth, idx) (wp + ((pth) * 7 + (idx)) * 16384)

    // path M (mean) on sM: mlp0 -> hbf00, spmm(bf) -> u0, mlp1 -> hbf01,
    // spmm(bf) -> u0, mlp2 -> h0 (fp32), final(h0)
    mlp_mma_kernel<<<gx, 256, SMEM_BYTES, sM>>>(
        MlpP{u0, WSLOT(0, 0), WSLOT(0, 1), mb1, mb2, nullptr, hb00}, n);
    spmm1_bf_kernel<<<spmm_blocks, 256, 0, sM>>>(hb00, meps, 1, u0, n);
    mlp_mma_kernel<<<gx, 256, SMEM_BYTES, sM>>>(
        MlpP{u0, WSLOT(0, 2), WSLOT(0, 3), mb1 + DIM, mb2 + DIM, nullptr, hb01}, n);
    spmm1_bf_kernel<<<spmm_blocks, 256, 0, sM>>>(hb01, meps, 2, u0, n);
    mlp_mma_kernel<<<gx, 256, SMEM_BYTES, sM>>>(
        MlpP{u0, WSLOT(0, 4), WSLOT(0, 5), mb1 + 2 * DIM, mb2 + 2 * DIM, h0, nullptr}, n);
    final_mma_kernel<<<gx, 256, SMEM_BYTES, sM>>>(
        FinP{h0, WSLOT(0, 6), mbo}, lng, lnb, out, 1, n);
    cudaEventRecord(s_evM, sM);

    // path S (std) on sS
    mlp_mma_kernel<<<gx, 256, SMEM_BYTES, sS>>>(
        MlpP{u1, WSLOT(1, 0), WSLOT(1, 1), sb1, sb2, nullptr, hb10}, n);
    spmm1_bf_kernel<<<spmm_blocks, 256, 0, sS>>>(hb10, seps, 1, u1, n);
    mlp_mma_kernel<<<gx, 256, SMEM_BYTES, sS>>>(
        MlpP{u1, WSLOT(1, 2), WSLOT(1, 3), sb1 + DIM, sb2 + DIM, nullptr, hb11}, n);
    spmm1_bf_kernel<<<spmm_blocks, 256, 0, sS>>>(hb11, seps, 2, u1, n);
    mlp_mma_kernel<<<gx, 256, SMEM_BYTES, sS>>>(
        MlpP{u1, WSLOT(1, 4), WSLOT(1, 5), sb1 + 2 * DIM, sb2 + 2 * DIM, h1, nullptr}, n);
    final_mma_kernel<<<gx, 256, SMEM_BYTES, sS>>>(
        FinP{h1, WSLOT(1, 6), sbo}, lng, lnb, out, 2, n);
    cudaEventRecord(s_evS, sS);

    // join and light sample on default stream
    cudaStreamWaitEvent(0, s_evM, 0);
    cudaStreamWaitEvent(0, s_evS, 0);
    cudaStreamWaitEvent(0, s_evN, 0);
    sample_kernel<<<(total / 4 + 255) / 256, 256>>>(out, epsbuf, total / 4);
}

// round 17
// speedup vs baseline: 1.0445x; 1.0030x over previous
#include <cuda_runtime.h>
#include <cuda_bf16.h>
#include <stdint.h>
#include <math.h>

#define DIM   128
#define MAXN  50000
#define MAXE  1600000
#define ND    (MAXN * DIM)
#define NDH   (MAXN * 64)

#define ASTR  68
#define A_HI  0
#define A_LO  8704
#define B_HI  17408
#define B_LO  26112
#define SMEM_BYTES 139264

#define SCAN_BLK 1024
#define MAX_PARTS 64

// ---------------- device scratch ----------------
__device__ int      g_deg[MAXN + 1];
__device__ int      g_rowptr[MAXN + 1];
__device__ int      g_cursor[MAXN + 1];
__device__ int      g_part[MAX_PARTS];
__device__ int      g_csrc[MAXE];
__device__ float    g_u[2 * ND];
__device__ float    g_h[2 * ND];
__device__ float    g_eps[ND];
__device__ uint32_t g_hbf[4 * NDH];      // [path][slot] packed bf16x2 h
__device__ uint32_t g_wprep[14 * 16384];

// ---------------- bf16 helpers ----------------
__device__ __forceinline__ uint32_t pack2bf(float x, float y) {
    unsigned short sx = __bfloat16_as_ushort(__float2bfloat16(x));
    unsigned short sy = __bfloat16_as_ushort(__float2bfloat16(y));
    return (uint32_t)sx | ((uint32_t)sy << 16);
}
__device__ __forceinline__ float bf_res(float x) {
    return x - __bfloat162float(__float2bfloat16(x));
}
__device__ __forceinline__ float bf_lo_f(uint32_t w) { return __uint_as_float(w << 16); }
__device__ __forceinline__ float bf_hi_f(uint32_t w) { return __uint_as_float(w & 0xFFFF0000u); }

__device__ __forceinline__ void mma_bf16(float* c, uint32_t a0, uint32_t a1, uint32_t a2,
                                         uint32_t a3, uint32_t b0, uint32_t b1) {
    asm volatile(
        "mma.sync.aligned.m16n8k16.row.col.f32.bf16.bf16.f32 "
        "{%0,%1,%2,%3},{%4,%5,%6,%7},{%8,%9},{%0,%1,%2,%3};"
        : "+f"(c[0]), "+f"(c[1]), "+f"(c[2]), "+f"(c[3])
        : "r"(a0), "r"(a1), "r"(a2), "r"(a3), "r"(b0), "r"(b1));
}

// ---------------- weight prep ----------------
struct PrepArgs { const float* src[14]; };

__global__ void prep_kernel(PrepArgs a) {
    extern __shared__ float tile[];          // 128 x 130
    const float* W = a.src[blockIdx.x];
    uint32_t* dhi = g_wprep + blockIdx.x * 16384;
    uint32_t* dlo = dhi + 8192;
    for (int idx = threadIdx.x; idx < 16384; idx += blockDim.x) {
        int k = idx >> 7, nc = idx & 127;
        tile[nc * 130 + k] = __ldg(&W[idx]);
    }
    __syncthreads();
    for (int idx = threadIdx.x; idx < 8192; idx += blockDim.x) {
        int nrow = idx >> 6, kp = idx & 63;
        float v0 = tile[nrow * 130 + kp * 2];
        float v1 = tile[nrow * 130 + kp * 2 + 1];
        dhi[idx] = pack2bf(v0, v1);
        dlo[idx] = pack2bf(bf_res(v0), bf_res(v1));
    }
}

// ---------------- CSR build ----------------
__global__ void zero_deg_kernel(int n) {
    int i = blockIdx.x * blockDim.x + threadIdx.x;
    if (i <= n) g_deg[i] = 0;
}
__global__ void hist_kernel(const int* __restrict__ dst, int e) {
    int i = blockIdx.x * blockDim.x + threadIdx.x;
    int i2 = i * 2;
    if (i2 + 1 < e) {
        int2 d = __ldg(&((const int2*)dst)[i]);
        atomicAdd(&g_deg[d.x], 1);
        atomicAdd(&g_deg[d.y], 1);
    } else if (i2 < e) {
        atomicAdd(&g_deg[dst[i2]], 1);
    }
}
__global__ void scan_p1(int n) {
    __shared__ int sd[32];
    int i = blockIdx.x * SCAN_BLK + threadIdx.x;
    int v = (i < n) ? g_deg[i] : 0;
#pragma unroll
    for (int o = 16; o > 0; o >>= 1) v += __shfl_xor_sync(0xffffffffu, v, o);
    if ((threadIdx.x & 31) == 0) sd[threadIdx.x >> 5] = v;
    __syncthreads();
    if (threadIdx.x < 32) {
        int s = sd[threadIdx.x];
#pragma unroll
        for (int o = 16; o > 0; o >>= 1) s += __shfl_xor_sync(0xffffffffu, s, o);
        if (threadIdx.x == 0) g_part[blockIdx.x] = s;
    }
}
__global__ void scan_p2(int nb) {
    int t = threadIdx.x;
    int v0 = (2 * t < nb) ? g_part[2 * t] : 0;
    int v1 = (2 * t + 1 < nb) ? g_part[2 * t + 1] : 0;
    int s = v0 + v1;
    int incl = s;
#pragma unroll
    for (int o = 1; o < 32; o <<= 1) {
        int u = __shfl_up_sync(0xffffffffu, incl, o);
        if (t >= o) incl += u;
    }
    int excl = incl - s;
    if (2 * t < MAX_PARTS) g_part[2 * t] = excl;
    if (2 * t + 1 < MAX_PARTS) g_part[2 * t + 1] = excl + v0;
}
__global__ void scan_p3(int n) {
    __shared__ int sw[32];
    int b = blockIdx.x, t = threadIdx.x;
    int i = b * SCAN_BLK + t;
    int v = (i < n) ? g_deg[i] : 0;
    int lane = t & 31, w = t >> 5;
    int incl = v;
#pragma unroll
    for (int o = 1; o < 32; o <<= 1) {
        int u = __shfl_up_sync(0xffffffffu, incl, o);
        if (lane >= o) incl += u;
    }
    if (lane == 31) sw[w] = incl;
    __syncthreads();
    if (t < 32) {
        int s = sw[t];
        int si = s;
#pragma unroll
        for (int o = 1; o < 32; o <<= 1) {
            int u = __shfl_up_sync(0xffffffffu, si, o);
            if (t >= o) si += u;
        }
        sw[t] = si - s;
    }
    __syncthreads();
    int excl = incl - v + sw[w] + g_part[b];
    if (i < n) {
        g_rowptr[i] = excl;
        g_cursor[i] = excl;
        if (i == n - 1) g_rowptr[n] = excl + v;
    }
}
__global__ void fill_kernel(const int* __restrict__ src, const int* __restrict__ dst, int e) {
    int i = blockIdx.x * blockDim.x + threadIdx.x;
    int i2 = i * 2;
    if (i2 + 1 < e) {
        int2 d = __ldg(&((const int2*)dst)[i]);
        int2 s = __ldg(&((const int2*)src)[i]);
        int p0 = atomicAdd(&g_cursor[d.x], 1);
        g_csrc[p0] = s.x;
        int p1 = atomicAdd(&g_cursor[d.y], 1);
        g_csrc[p1] = s.y;
    } else if (i2 < e) {
        int p = atomicAdd(&g_cursor[dst[i2]], 1);
        g_csrc[p] = src[i2];
    }
}

// ---------------- layer-0 SpMM (fp32 x, paths share gather) ----------------
__global__ void spmm0_kernel(const float* __restrict__ x,
                             const float* __restrict__ epsm, const float* __restrict__ epss,
                             float* __restrict__ um, float* __restrict__ us, int n) {
    int gw = (blockIdx.x * blockDim.x + threadIdx.x) >> 5;
    int lane = threadIdx.x & 31;
    if (gw >= n) return;
    int rp0 = g_rowptr[gw], rp1 = g_rowptr[gw + 1];
    const float4* x4 = (const float4*)x;
    float4 am = make_float4(0.f, 0.f, 0.f, 0.f);
#pragma unroll 2
    for (int j = rp0; j < rp1; ++j) {
        int s = __ldg(&g_csrc[j]);
        float4 v = __ldg(&x4[(size_t)s * 32 + lane]);
        am.x += v.x; am.y += v.y; am.z += v.z; am.w += v.w;
    }
    float cm = 1.0f + __ldg(&epsm[0]);
    float cs = 1.0f + __ldg(&epss[0]);
    float4 h0 = __ldg(&x4[(size_t)gw * 32 + lane]);
    float4 om, os;
    om.x = fmaf(cm, h0.x, am.x); om.y = fmaf(cm, h0.y, am.y);
    om.z = fmaf(cm, h0.z, am.z); om.w = fmaf(cm, h0.w, am.w);
    os.x = fmaf(cs, h0.x, am.x); os.y = fmaf(cs, h0.y, am.y);
    os.z = fmaf(cs, h0.z, am.z); os.w = fmaf(cs, h0.w, am.w);
    ((float4*)um)[(size_t)gw * 32 + lane] = om;
    ((float4*)us)[(size_t)gw * 32 + lane] = os;
}

// ---------------- per-path SpMM over packed bf16 h (half traffic) ----------------
__global__ void spmm1_bf_kernel(const uint32_t* __restrict__ hbf,
                                const float* __restrict__ epsv, int layer,
                                float* __restrict__ u, int n) {
    int gw = (blockIdx.x * blockDim.x + threadIdx.x) >> 5;
    int lane = threadIdx.x & 31;
    if (gw >= n) return;
    int rp0 = g_rowptr[gw], rp1 = g_rowptr[gw + 1];
    const uint2* h2 = (const uint2*)hbf;    // row = 32 uint2 (64 words = 128 bf16)
    float a0 = 0.f, a1 = 0.f, a2 = 0.f, a3 = 0.f;
#pragma unroll 2
    for (int j = rp0; j < rp1; ++j) {
        int s = __ldg(&g_csrc[j]);
        uint2 w = __ldg(&h2[(size_t)s * 32 + lane]);
        a0 += bf_lo_f(w.x); a1 += bf_hi_f(w.x);
        a2 += bf_lo_f(w.y); a3 += bf_hi_f(w.y);
    }
    float c = 1.0f + __ldg(&epsv[layer]);
    uint2 hw = __ldg(&h2[(size_t)gw * 32 + lane]);
    float4 o;
    o.x = fmaf(c, bf_lo_f(hw.x), a0);
    o.y = fmaf(c, bf_hi_f(hw.x), a1);
    o.z = fmaf(c, bf_lo_f(hw.y), a2);
    o.w = fmaf(c, bf_hi_f(hw.y), a3);
    ((float4*)u)[(size_t)gw * 32 + lane] = o;
}

// ---------------- shared GEMM pieces ----------------
__device__ __forceinline__ void load_A_bf(const float* __restrict__ U, int row0, int n,
                                          uint32_t* smw, int t) {
    int row = t >> 1, half = t & 1;
    int r = row0 + row;
    const float4* u4 = (const float4*)U + (size_t)r * 32 + half * 16;
    uint32_t* ah = smw + A_HI + row * ASTR + half * 32;
    uint32_t* al = smw + A_LO + row * ASTR + half * 32;
#pragma unroll 4
    for (int q = 0; q < 16; q++) {
        float4 v = make_float4(0.f, 0.f, 0.f, 0.f);
        if (r < n) v = __ldg(&u4[q]);
        ah[q * 2]     = pack2bf(v.x, v.y);
        al[q * 2]     = pack2bf(bf_res(v.x), bf_res(v.y));
        ah[q * 2 + 1] = pack2bf(v.z, v.w);
        al[q * 2 + 1] = pack2bf(bf_res(v.z), bf_res(v.w));
    }
}

__device__ __forceinline__ void copy_W(const uint32_t* __restrict__ Wp, uint32_t* smw, int t) {
    const uint4* s4 = (const uint4*)Wp;
#pragma unroll
    for (int i = 0; i < 8; i++) {
        int j = t + i * 256;
        int nrow = j >> 4, kp = (j & 15) * 4;
        *(uint4*)(smw + B_HI + nrow * ASTR + kp) = __ldg(&s4[j]);
        *(uint4*)(smw + B_LO + nrow * ASTR + kp) = __ldg(&s4[j + 2048]);
    }
}

__device__ __forceinline__ void gemm_pass(const uint32_t* __restrict__ smw, int aoff, int boff,
                                          float acc[2][8][4], int ra, int kq, int nb) {
#pragma unroll
    for (int kk = 0; kk < 8; kk++) {
        int kp0 = kk * 8 + kq, kp1 = kp0 + 4;
        uint32_t a[2][4];
#pragma unroll
        for (int i = 0; i < 2; i++) {
            int rb = aoff + (ra + i * 16) * ASTR;
            a[i][0] = smw[rb + kp0];
            a[i][1] = smw[rb + 8 * ASTR + kp0];
            a[i][2] = smw[rb + kp1];
            a[i][3] = smw[rb + 8 * ASTR + kp1];
        }
#pragma unroll
        for (int j = 0; j < 8; j++) {
            int bb = boff + (nb + j * 8) * ASTR;
            uint32_t b0 = smw[bb + kp0], b1 = smw[bb + kp1];
            mma_bf16(acc[0][j], a[0][0], a[0][1], a[0][2], a[0][3], b0, b1);
            mma_bf16(acc[1][j], a[1][0], a[1][1], a[1][2], a[1][3], b0, b1);
        }
    }
}

__device__ __forceinline__ void gemm3(const uint32_t* smw, float acc[2][8][4],
                                      int ra, int kq, int nb) {
    gemm_pass(smw, A_HI, B_HI, acc, ra, kq, nb);
    gemm_pass(smw, A_HI, B_LO, acc, ra, kq, nb);
    gemm_pass(smw, A_LO, B_HI, acc, ra, kq, nb);
}

__device__ __forceinline__ void zero_acc(float acc[2][8][4]) {
#pragma unroll
    for (int i = 0; i < 2; i++)
#pragma unroll
        for (int j = 0; j < 8; j++)
#pragma unroll
            for (int q = 0; q < 4; q++) acc[i][j][q] = 0.f;
}

__device__ __forceinline__ float sigf(float x) { return 1.0f / (1.0f + expf(-x)); }

// ---------------- MLP layer (single path) ----------------
// Hf != nullptr: write fp32 H; else write packed bf16 to Hbf (256B/row)
struct MlpP { const float* U; const uint32_t* W1p; const uint32_t* W2p;
              const float* b1; const float* b2; float* Hf; uint32_t* Hbf; };

__global__ __launch_bounds__(256, 1) void mlp_mma_kernel(MlpP P, int n) {
    extern __shared__ uint32_t smw[];
    int row0 = blockIdx.x * 128;
    int t = threadIdx.x, lane = t & 31, wid = t >> 5;
    int wm = wid >> 1, wn = wid & 1;
    int ra = wm * 32 + (lane >> 2);
    int kq = lane & 3;
    int nb = wn * 64 + (lane >> 2);

    load_A_bf(P.U, row0, n, smw, t);
    copy_W(P.W1p, smw, t);
    __syncthreads();

    float acc[2][8][4];
    zero_acc(acc);
    gemm3(smw, acc, ra, kq, nb);
    __syncthreads();

#pragma unroll
    for (int i = 0; i < 2; i++) {
#pragma unroll
        for (int j = 0; j < 8; j++) {
            int rl = wm * 32 + i * 16 + (lane >> 2);
            int c0 = wn * 64 + j * 8 + 2 * kq;
            float s0 = sigf(acc[i][j][0] + __ldg(&P.b1[c0]));
            float s1 = sigf(acc[i][j][1] + __ldg(&P.b1[c0 + 1]));
            float s2 = sigf(acc[i][j][2] + __ldg(&P.b1[c0]));
            float s3 = sigf(acc[i][j][3] + __ldg(&P.b1[c0 + 1]));
            int kp = wn * 32 + j * 4 + kq;
            smw[A_HI + rl * ASTR + kp] = pack2bf(s0, s1);
            smw[A_LO + rl * ASTR + kp] = pack2bf(bf_res(s0), bf_res(s1));
            smw[A_HI + (rl + 8) * ASTR + kp] = pack2bf(s2, s3);
            smw[A_LO + (rl + 8) * ASTR + kp] = pack2bf(bf_res(s2), bf_res(s3));
        }
    }
    copy_W(P.W2p, smw, t);
    __syncthreads();

    zero_acc(acc);
    gemm3(smw, acc, ra, kq, nb);

#pragma unroll
    for (int i = 0; i < 2; i++) {
#pragma unroll
        for (int j = 0; j < 8; j++) {
            int gr = row0 + wm * 32 + i * 16 + (lane >> 2);
            int c0 = wn * 64 + j * 8 + 2 * kq;
            float bb0 = __ldg(&P.b2[c0]), bb1 = __ldg(&P.b2[c0 + 1]);
            float v0 = acc[i][j][0] + bb0, v1 = acc[i][j][1] + bb1;
            float v2 = acc[i][j][2] + bb0, v3 = acc[i][j][3] + bb1;
            if (P.Hf) {
                if (gr < n)
                    *(float2*)(P.Hf + (size_t)gr * DIM + c0) = make_float2(v0, v1);
                if (gr + 8 < n)
                    *(float2*)(P.Hf + (size_t)(gr + 8) * DIM + c0) = make_float2(v2, v3);
            } else {
                int wc = (c0 >> 1);          // word column 0..63
                if (gr < n) P.Hbf[(size_t)gr * 64 + wc] = pack2bf(v0, v1);
                if (gr + 8 < n) P.Hbf[(size_t)(gr + 8) * 64 + wc] = pack2bf(v2, v3);
            }
        }
    }
}

// ---------------- final (single path): LN(Hin @ Wout + bout) -> out section ----------------
struct FinP { const float* Hin; const uint32_t* Wp; const float* bo; };

__global__ __launch_bounds__(256, 1) void final_mma_kernel(FinP P,
                                                           const float* __restrict__ gamma,
                                                           const float* __restrict__ beta,
                                                           float* __restrict__ out,
                                                           int sect, int n) {
    extern __shared__ uint32_t smw[];
    int row0 = blockIdx.x * 128;
    int t = threadIdx.x, lane = t & 31, wid = t >> 5;
    int wm = wid >> 1, wn = wid & 1;
    int ra = wm * 32 + (lane >> 2);
    int kq = lane & 3;
    int nb = wn * 64 + (lane >> 2);

    load_A_bf(P.Hin, row0, n, smw, t);
    copy_W(P.Wp, smw, t);
    __syncthreads();

    float acc[2][8][4];
    zero_acc(acc);
    gemm3(smw, acc, ra, kq, nb);
    __syncthreads();

    float* gS = (float*)smw;
#pragma unroll
    for (int i = 0; i < 2; i++) {
#pragma unroll
        for (int j = 0; j < 8; j++) {
            int rl = wm * 32 + i * 16 + (lane >> 2);
            int c0 = wn * 64 + j * 8 + 2 * kq;
            float bb0 = __ldg(&P.bo[c0]), bb1 = __ldg(&P.bo[c0 + 1]);
            gS[rl * 133 + c0]       = acc[i][j][0] + bb0;
            gS[rl * 133 + c0 + 1]   = acc[i][j][1] + bb1;
            gS[(rl + 8) * 133 + c0]     = acc[i][j][2] + bb0;
            gS[(rl + 8) * 133 + c0 + 1] = acc[i][j][3] + bb1;
        }
    }
    __syncthreads();

    if (t < 128) {
        int r = row0 + t;
        if (r < n) {
            const float* rowp = gS + t * 133;
            float sum = 0.f;
#pragma unroll 8
            for (int c = 0; c < 128; c++) sum += rowp[c];
            float mean = sum * (1.0f / 128.0f);
            float ss = 0.f;
#pragma unroll 8
            for (int c = 0; c < 128; c++) {
                float d = rowp[c] - mean;
                ss += d * d;
            }
            float inv = rsqrtf(ss * (1.0f / 128.0f) + 1e-5f);
            float* op = out + (size_t)sect * (size_t)n * DIM + (size_t)r * DIM;
#pragma unroll 4
            for (int c = 0; c < 128; c += 4) {
                float4 o;
                o.x = fmaf((rowp[c]     - mean) * inv, __ldg(&gamma[c]),     __ldg(&beta[c]));
                o.y = fmaf((rowp[c + 1] - mean) * inv, __ldg(&gamma[c + 1]), __ldg(&beta[c + 1]));
                o.z = fmaf((rowp[c + 2] - mean) * inv, __ldg(&gamma[c + 2]), __ldg(&beta[c + 2]));
                o.w = fmaf((rowp[c + 3] - mean) * inv, __ldg(&gamma[c + 3]), __ldg(&beta[c + 3]));
                *(float4*)(op + c) = o;
            }
        }
    }
}

// ---------------- threefry noise (persistent grid) + light sample join ----------------
__device__ __forceinline__ uint32_t rotl32(uint32_t x, int r) {
    return (x << r) | (x >> (32 - r));
}
__device__ __forceinline__ float bits_to_normal(uint32_t b) {
    uint32_t fb = (b >> 9) | 0x3F800000u;
    float u = __uint_as_float(fb) - 1.0f;
    const float lo = -0.99999994f;
    float v = fmaf(u, 2.0f, lo);
    v = fmaxf(v, lo);
    float w = -log1pf(-v * v);
    float p;
    if (w < 5.0f) {
        w -= 2.5f;
        p = 2.81022636e-08f;
        p = fmaf(p, w, 3.43273939e-07f);
        p = fmaf(p, w, -3.5233877e-06f);
        p = fmaf(p, w, -4.39150654e-06f);
        p = fmaf(p, w, 0.00021858087f);
        p = fmaf(p, w, -0.00125372503f);
        p = fmaf(p, w, -0.00417768164f);
        p = fmaf(p, w, 0.246640727f);
        p = fmaf(p, w, 1.50140941f);
    } else {
        w = sqrtf(w) - 3.0f;
        p = -0.000200214257f;
        p = fmaf(p, w, 0.000100950558f);
        p = fmaf(p, w, 0.00134934322f);
        p = fmaf(p, w, -0.00367342844f);
        p = fmaf(p, w, 0.00573950773f);
        p = fmaf(p, w, -0.0076224613f);
        p = fmaf(p, w, 0.00943887047f);
        p = fmaf(p, w, 1.00167406f);
        p = fmaf(p, w, 2.83297682f);
    }
    return 1.41421356237f * (p * v);
}

__global__ void noise_kernel(float* __restrict__ eps, int total) {
    int stride = gridDim.x * blockDim.x;
    for (int f = blockIdx.x * blockDim.x + threadIdx.x; f < total; f += stride) {
        const uint32_t ks0 = 0u, ks1 = 42u;
        const uint32_t ks2 = ks0 ^ ks1 ^ 0x1BD11BDAu;
        uint32_t x0 = 0u + ks0;
        uint32_t x1 = (uint32_t)f + ks1;
#define TFR(r) { x0 += x1; x1 = rotl32(x1, (r)) ^ x0; }
        TFR(13) TFR(15) TFR(26) TFR(6)   x0 += ks1; x1 += ks2 + 1u;
        TFR(17) TFR(29) TFR(16) TFR(24)  x0 += ks2; x1 += ks0 + 2u;
        TFR(13) TFR(15) TFR(26) TFR(6)   x0 += ks0; x1 += ks1 + 3u;
        TFR(17) TFR(29) TFR(16) TFR(24)  x0 += ks1; x1 += ks2 + 4u;
        TFR(13) TFR(15) TFR(26) TFR(6)   x0 += ks2; x1 += ks0 + 5u;
#undef TFR
        eps[f] = bits_to_normal(x0 ^ x1);
    }
}

__global__ void sample_kernel(float* __restrict__ out, const float* __restrict__ eps,
                              int total4) {
    int f = blockIdx.x * blockDim.x + threadIdx.x;
    if (f >= total4) return;
    const float4* mv = (const float4*)out + total4;
    const float4* sv = (const float4*)out + 2 * (size_t)total4;
    float4 ev = __ldg(&((const float4*)eps)[f]);
    float4 m = __ldg(&mv[f]);
    float4 s = __ldg(&sv[f]);
    float4 o;
    o.x = fmaf(ev.x, s.x, m.x);
    o.y = fmaf(ev.y, s.y, m.y);
    o.z = fmaf(ev.z, s.z, m.z);
    o.w = fmaf(ev.w, s.w, m.w);
    ((float4*)out)[f] = o;
}

// ---------------- persistent stream/event handles ----------------
static cudaStream_t s_sM = nullptr, s_sS = nullptr, s_sN = nullptr;
static cudaEvent_t  s_ev0, s_evP, s_evF, s_evR, s_evM, s_evS, s_evN;

// ---------------- launch ----------------
extern "C" void kernel_launch(void* const* d_in, const int* in_sizes, int n_in,
                              void* d_out, int out_size) {
    const float* x    = (const float*)d_in[0];
    const int*   esrc = (const int*)d_in[1];
    const int*   edst = (const int*)d_in[2];
    const float* mW1  = (const float*)d_in[3];
    const float* mb1  = (const float*)d_in[4];
    const float* mW2  = (const float*)d_in[5];
    const float* mb2  = (const float*)d_in[6];
    const float* meps = (const float*)d_in[7];
    const float* mWo  = (const float*)d_in[8];
    const float* mbo  = (const float*)d_in[9];
    const float* sW1  = (const float*)d_in[10];
    const float* sb1  = (const float*)d_in[11];
    const float* sW2  = (const float*)d_in[12];
    const float* sb2  = (const float*)d_in[13];
    const float* seps = (const float*)d_in[14];
    const float* sWo  = (const float*)d_in[15];
    const float* sbo  = (const float*)d_in[16];
    const float* lng  = (const float*)d_in[17];
    const float* lnb  = (const float*)d_in[18];

    int n = in_sizes[0] / DIM;
    int e = in_sizes[1];
    int total = n * DIM;
    float* out = (float*)d_out;

    void* p;
    cudaGetSymbolAddress(&p, g_u); float* u0 = (float*)p; float* u1 = u0 + ND;
    cudaGetSymbolAddress(&p, g_h); float* h0 = (float*)p; float* h1 = h0 + ND;
    cudaGetSymbolAddress(&p, g_eps); float* epsbuf = (float*)p;
    cudaGetSymbolAddress(&p, g_hbf); uint32_t* hb = (uint32_t*)p;
    uint32_t* hb00 = hb;            uint32_t* hb01 = hb + NDH;
    uint32_t* hb10 = hb + 2 * NDH;  uint32_t* hb11 = hb + 3 * NDH;
    cudaGetSymbolAddress(&p, g_wprep); uint32_t* wp = (uint32_t*)p;

    cudaFuncSetAttribute(mlp_mma_kernel, cudaFuncAttributeMaxDynamicSharedMemorySize, SMEM_BYTES);
    cudaFuncSetAttribute(final_mma_kernel, cudaFuncAttributeMaxDynamicSharedMemorySize, SMEM_BYTES);
    cudaFuncSetAttribute(prep_kernel, cudaFuncAttributeMaxDynamicSharedMemorySize, 128 * 130 * 4);

    if (s_sM == nullptr) {
        cudaStreamCreateWithFlags(&s_sM, cudaStreamNonBlocking);
        cudaStreamCreateWithFlags(&s_sS, cudaStreamNonBlocking);
        cudaStreamCreateWithFlags(&s_sN, cudaStreamNonBlocking);
        cudaEventCreateWithFlags(&s_ev0, cudaEventDisableTiming);
        cudaEventCreateWithFlags(&s_evP, cudaEventDisableTiming);
        cudaEventCreateWithFlags(&s_evF, cudaEventDisableTiming);
        cudaEventCreateWithFlags(&s_evR, cudaEventDisableTiming);
        cudaEventCreateWithFlags(&s_evM, cudaEventDisableTiming);
        cudaEventCreateWithFlags(&s_evS, cudaEventDisableTiming);
        cudaEventCreateWithFlags(&s_evN, cudaEventDisableTiming);
    }
    cudaStream_t sM = s_sM, sS = s_sS, sN = s_sN;

    // fork point
    cudaEventRecord(s_ev0, 0);
    cudaStreamWaitEvent(sM, s_ev0, 0);

    // weight prep on sM, overlapping CSR build on the default stream
    PrepArgs pa;
    for (int pth = 0; pth < 2; pth++) {
        const float* W1 = pth ? sW1 : mW1;
        const float* W2 = pth ? sW2 : mW2;
        const float* Wo = pth ? sWo : mWo;
        for (int l = 0; l < 3; l++) {
            pa.src[pth * 7 + l * 2 + 0] = W1 + l * 16384;
            pa.src[pth * 7 + l * 2 + 1] = W2 + l * 16384;
        }
        pa.src[pth * 7 + 6] = Wo;
    }
    prep_kernel<<<14, 256, 128 * 130 * 4, sM>>>(pa);
    cudaEventRecord(s_evP, sM);

    // CSR by destination (default stream), int2-vectorized hist/fill
    int nblk = (n + SCAN_BLK - 1) / SCAN_BLK;
    zero_deg_kernel<<<(n + 256) / 256, 256>>>(n);
    hist_kernel<<<(e / 2 + 256) / 256, 256>>>(edst, e);
    scan_p1<<<nblk, SCAN_BLK>>>(n);
    scan_p2<<<1, 32>>>(nblk);
    scan_p3<<<nblk, SCAN_BLK>>>(n);
    fill_kernel<<<(e / 2 + 256) / 256, 256>>>(esrc, edst, e);
    cudaEventRecord(s_evF, 0);

    int spmm_blocks = (n * 32 + 255) / 256;
    int gx = (n + 127) / 128;

    // noise: persistent 148-CTA grid on sN, co-runs with spmm0
    cudaStreamWaitEvent(sN, s_evF, 0);
    noise_kernel<<<148, 256, 0, sN>>>(epsbuf, total);
    cudaEventRecord(s_evN, sN);

    // layer 0: shared x gather (default stream), then symmetric fork
    spmm0_kernel<<<spmm_blocks, 256>>>(x, meps, seps, u0, u1, n);
    cudaEventRecord(s_evR, 0);
    cudaStreamWaitEvent(sM, s_evR, 0);
    cudaStreamWaitEvent(sS, s_evR, 0);
    cudaStreamWaitEvent(sS, s_evP, 0);

#define WSLOT(pth, idx) (wp + ((pth) * 7 + (idx)) * 16384)

    // path M (mean) on sM: mlp0 -> hbf00, spmm(bf) -> u0, mlp1 -> hbf01,
    // spmm(bf) -> u0, mlp2 -> h0 (fp32), final(h0)
    mlp_mma_kernel<<<gx, 256, SMEM_BYTES, sM>>>(
        MlpP{u0, WSLOT(0, 0), WSLOT(0, 1), mb1, mb2, nullptr, hb00}, n);
    spmm1_bf_kernel<<<spmm_blocks, 256, 0, sM>>>(hb00, meps, 1, u0, n);
    mlp_mma_kernel<<<gx, 256, SMEM_BYTES, sM>>>(
        MlpP{u0, WSLOT(0, 2), WSLOT(0, 3), mb1 + DIM, mb2 + DIM, nullptr, hb01}, n);
    spmm1_bf_kernel<<<spmm_blocks, 256, 0, sM>>>(hb01, meps, 2, u0, n);
    mlp_mma_kernel<<<gx, 256, SMEM_BYTES, sM>>>(
        MlpP{u0, WSLOT(0, 4), WSLOT(0, 5), mb1 + 2 * DIM, mb2 + 2 * DIM, h0, nullptr}, n);
    final_mma_kernel<<<gx, 256, SMEM_BYTES, sM>>>(
        FinP{h0, WSLOT(0, 6), mbo}, lng, lnb, out, 1, n);
    cudaEventRecord(s_evM, sM);

    // path S (std) on sS
    mlp_mma_kernel<<<gx, 256, SMEM_BYTES, sS>>>(
        MlpP{u1, WSLOT(1, 0), WSLOT(1, 1), sb1, sb2, nullptr, hb10}, n);
    spmm1_bf_kernel<<<spmm_blocks, 256, 0, sS>>>(hb10, seps, 1, u1, n);
    mlp_mma_kernel<<<gx, 256, SMEM_BYTES, sS>>>(
        MlpP{u1, WSLOT(1, 2), WSLOT(1, 3), sb1 + DIM, sb2 + DIM, nullptr, hb11}, n);
    spmm1_bf_kernel<<<spmm_blocks, 256, 0, sS>>>(hb11, seps, 2, u1, n);
    mlp_mma_kernel<<<gx, 256, SMEM_BYTES, sS>>>(
        MlpP{u1, WSLOT(1, 4), WSLOT(1, 5), sb1 + 2 * DIM, sb2 + 2 * DIM, h1, nullptr}, n);
    final_mma_kernel<<<gx, 256, SMEM_BYTES, sS>>>(
        FinP{h1, WSLOT(1, 6), sbo}, lng, lnb, out, 2, n);
    cudaEventRecord(s_evS, sS);

    // join and light sample on default stream
    cudaStreamWaitEvent(0, s_evM, 0);
    cudaStreamWaitEvent(0, s_evS, 0);
    cudaStreamWaitEvent(0, s_evN, 0);
    sample_kernel<<<(total / 4 + 255) / 256, 256>>>(out, epsbuf, total / 4);
}